// round 10
// baseline (speedup 1.0000x reference)
#include <cuda_runtime.h>
#include <math.h>

#define HH 768
#define SS 128
#define LL 10

typedef unsigned long long ull;

// Scratch (no allocation allowed)
__device__ float g_hp[4][2][SS * HH];      // k-split partials of x@W
__device__ float g_h[2][SS * HH];          // x@W + bias (reduced)
__device__ float g_u[2][SS * 20];          // x@A   (rl = r*10+l)
__device__ float g_Bt[2 * LL * 2 * HH];    // Bt[mat][l][r][i] = B[mat][(r*H+i)*L + l]
__device__ float g_ct[LL * HH];            // ct[l][i] = 0.5 * classifier[i*L + l]
__device__ float g_ab[2][LL * SS * HH];    // a[l][s][i], b[l][t][i]
__device__ float g_cab[2][LL * SS];        // Ca[l][s] = sum_i ct*a ; Cb[l][t]

// Packed f32x2 ops (sm_100+). ptxas will not auto-emit these.
#define ADD2(o,a,b)   asm("add.rn.f32x2 %0,%1,%2;"    : "=l"(o) : "l"(a), "l"(b))
#define MUL2(o,a,b)   asm("mul.rn.f32x2 %0,%1,%2;"    : "=l"(o) : "l"(a), "l"(b))
#define FMA2(o,a,b,c) asm("fma.rn.f32x2 %0,%1,%2,%3;" : "=l"(o) : "l"(a), "l"(b), "l"(c))

// ---------------------------------------------------------------------------
// Prep kernel, 528 blocks x 256 threads:
//   blocks 0..383   : gemm partials (2 mats x 12 i-tiles x 4 s-tiles x 4 ksplit)
//   blocks 384..511 : u[s][r][l]
//   blocks 512..527 : transposes (Bt, ct)
// ---------------------------------------------------------------------------
__global__ void __launch_bounds__(256) prep_kernel(
        const float* __restrict__ x,
        const float* __restrict__ Wsrc, const float* __restrict__ Wtgt,
        const float* __restrict__ Asrc, const float* __restrict__ Bsrc,
        const float* __restrict__ Atgt, const float* __restrict__ Btgt,
        const float* __restrict__ cls) {
    const int bid = blockIdx.x;
    const int tid = threadIdx.x;

    if (bid < 384) {
        // ---- gemm partial: 32s x 64i tile, k-range 192 (6 chunks of 32) ----
        const int p    = bid & 3;
        const int rest = bid >> 2;
        const int it   = rest % 12;
        const int st   = (rest / 12) % 4;
        const int mat  = rest / 48;
        const float* __restrict__ Wm = mat ? Wtgt : Wsrc;
        const int i0 = it * 64;
        const int s0 = st * 32;
        const int kb = p * 192;

        __shared__ float sX[32][34];                  // [k][s], pad 34: 8B-aligned
        __shared__ __align__(16) float sW[32][64];    // [k][i]

        const int tx  = tid & 15;       // i (4 each)
        const int ty  = tid >> 4;       // s (2 each)
        const int kx  = tid & 31;       // staging: k lane
        const int sw  = tid >> 5;       // staging: s base (rows sw+8j)
        const int kkw = tid >> 4;       // staging: W row
        const int iw  = (tid & 15) * 4; // staging: W col

        ull acc00 = 0, acc01 = 0, acc10 = 0, acc11 = 0;

        float px[4]; float4 pw0, pw1;
        #pragma unroll
        for (int j = 0; j < 4; j++)
            px[j] = x[(s0 + sw + 8 * j) * HH + kb + kx];
        pw0 = *(const float4*)&Wm[(kb + kkw) * HH + i0 + iw];
        pw1 = *(const float4*)&Wm[(kb + 16 + kkw) * HH + i0 + iw];

        for (int c = 0; c < 6; c++) {
            __syncthreads();
            #pragma unroll
            for (int j = 0; j < 4; j++) sX[kx][sw + 8 * j] = px[j];
            *(float4*)&sW[kkw][iw]      = pw0;
            *(float4*)&sW[kkw + 16][iw] = pw1;
            __syncthreads();
            if (c < 5) {
                const int k0 = kb + (c + 1) * 32;
                #pragma unroll
                for (int j = 0; j < 4; j++)
                    px[j] = x[(s0 + sw + 8 * j) * HH + k0 + kx];
                pw0 = *(const float4*)&Wm[(k0 + kkw) * HH + i0 + iw];
                pw1 = *(const float4*)&Wm[(k0 + 16 + kkw) * HH + i0 + iw];
            }
            #pragma unroll
            for (int kk = 0; kk < 32; kk++) {
                float2 a2 = *(const float2*)&sX[kk][ty * 2];
                ull b01 = *(const ull*)&sW[kk][tx * 4];
                ull b23 = *(const ull*)&sW[kk][tx * 4 + 2];
                ull a0d, a1d;
                asm("mov.b64 %0,{%1,%1};" : "=l"(a0d) : "f"(a2.x));
                asm("mov.b64 %0,{%1,%1};" : "=l"(a1d) : "f"(a2.y));
                FMA2(acc00, a0d, b01, acc00);
                FMA2(acc01, a0d, b23, acc01);
                FMA2(acc10, a1d, b01, acc10);
                FMA2(acc11, a1d, b23, acc11);
            }
        }
        float v[2][4];
        asm("mov.b64 {%0,%1}, %2;" : "=f"(v[0][0]), "=f"(v[0][1]) : "l"(acc00));
        asm("mov.b64 {%0,%1}, %2;" : "=f"(v[0][2]), "=f"(v[0][3]) : "l"(acc01));
        asm("mov.b64 {%0,%1}, %2;" : "=f"(v[1][0]), "=f"(v[1][1]) : "l"(acc10));
        asm("mov.b64 {%0,%1}, %2;" : "=f"(v[1][2]), "=f"(v[1][3]) : "l"(acc11));
        #pragma unroll
        for (int i = 0; i < 2; i++)
            #pragma unroll
            for (int j = 0; j < 4; j++) {
                int s  = s0 + ty * 2 + i;
                int ii = i0 + tx * 4 + j;
                g_hp[p][mat][s * HH + ii] = v[i][j];
            }
    } else if (bid < 512) {
        // ---- u[s][r][l] = sum_h x[s,h]*A[h,r,l], 4-way k-split ----
        __shared__ float sx[HH];
        __shared__ float spart[4][40];
        const int s = bid - 384;
        for (int e = tid; e < HH; e += 256) sx[e] = x[s * HH + e];
        __syncthreads();
        const int seg = tid >> 6;
        const int j   = tid & 63;
        if (j < 40) {
            const int mat = j / 20, rl = j % 20;
            const float* __restrict__ A = mat ? Atgt : Asrc;
            float acc = 0.f;
            const int h0 = seg * 192;
            #pragma unroll 8
            for (int h = h0; h < h0 + 192; h++)
                acc = fmaf(sx[h], A[h * 20 + rl], acc);
            spart[seg][j] = acc;
        }
        __syncthreads();
        if (tid < 40) {
            float vv = spart[0][tid] + spart[1][tid] + spart[2][tid] + spart[3][tid];
            g_u[tid / 20][s * 20 + tid % 20] = vv;
        }
    } else {
        // ---- transposes: Bt and ct ----
        const int idx0 = (bid - 512) * 256 + tid;
        for (int n = idx0; n < 2 * LL * 2 * HH; n += 16 * 256) {
            int i   = n % HH;
            int rem = n / HH;
            int r   = rem % 2;
            int l   = (rem / 2) % LL;
            int mat = rem / (2 * LL);
            const float* __restrict__ Bm = mat ? Btgt : Bsrc;
            g_Bt[((mat * LL + l) * 2 + r) * HH + i] = Bm[(r * HH + i) * LL + l];
        }
        for (int n = idx0; n < LL * HH; n += 16 * 256) {
            int i = n % HH, l = n / HH;
            g_ct[l * HH + i] = 0.5f * cls[i * LL + l];
        }
    }
}

// ---------------------------------------------------------------------------
// Reduce kernel: g_h = sum_p g_hp[p] + bias.  192 blocks x 256 thr, 1 float4 each.
// ---------------------------------------------------------------------------
__global__ void __launch_bounds__(256) reduce_h_kernel(
        const float* __restrict__ bsrc, const float* __restrict__ btgt) {
    const int n4  = blockIdx.x * 256 + threadIdx.x;    // float4 index
    const int mat = n4 / (SS * HH / 4);
    const int off = (n4 - mat * (SS * HH / 4)) * 4;
    const int i   = off % HH;
    const float* __restrict__ bm = mat ? btgt : bsrc;

    float4 h0 = *(const float4*)&g_hp[0][mat][off];
    float4 h1 = *(const float4*)&g_hp[1][mat][off];
    float4 h2 = *(const float4*)&g_hp[2][mat][off];
    float4 h3 = *(const float4*)&g_hp[3][mat][off];
    float4 bb = *(const float4*)&bm[i];
    float4 v;
    v.x = ((h0.x + h1.x) + (h2.x + h3.x)) + bb.x;
    v.y = ((h0.y + h1.y) + (h2.y + h3.y)) + bb.y;
    v.z = ((h0.z + h1.z) + (h2.z + h3.z)) + bb.z;
    v.w = ((h0.w + h1.w) + (h2.w + h3.w)) + bb.w;
    *(float4*)&g_h[mat][off] = v;
}

// ---------------------------------------------------------------------------
// Expand kernel: ab = h + u0*Bt0 + u1*Bt1 ; Ca/Cb = sum_i ct*ab  (rank-1 part)
// grid (8 s-chunks, LL, 2 mats) = 160 blocks, 256 threads.
// ---------------------------------------------------------------------------
__global__ void __launch_bounds__(256) expand_kernel() {
    const int mat = blockIdx.z;
    const int l   = blockIdx.y;
    const int s0  = blockIdx.x * 16;
    const int tid = threadIdx.x;

    __shared__ __align__(16) float sBt0[HH], sBt1[HH], sCt[HH];
    __shared__ float su[16][2];

    for (int e = tid; e < HH; e += 256) {
        sBt0[e] = g_Bt[((mat * LL + l) * 2 + 0) * HH + e];
        sBt1[e] = g_Bt[((mat * LL + l) * 2 + 1) * HH + e];
        sCt[e]  = g_ct[l * HH + e];
    }
    if (tid < 32) {
        int si = tid >> 1, r = tid & 1;
        su[si][r] = g_u[mat][(s0 + si) * 20 + r * 10 + l];
    }
    __syncthreads();

    const int row    = tid >> 4;
    const int lane16 = tid & 15;
    const float u0 = su[row][0], u1 = su[row][1];
    const float* __restrict__ hrow = &g_h[mat][(s0 + row) * HH];
    float* __restrict__ orow = &g_ab[mat][(l * SS + s0 + row) * HH];

    float ca = 0.f;
    #pragma unroll
    for (int j = 0; j < 12; j++) {
        int i4 = lane16 * 4 + j * 64;
        float4 h4 = *(const float4*)&hrow[i4];
        float4 q0 = *(const float4*)&sBt0[i4];
        float4 q1 = *(const float4*)&sBt1[i4];
        float4 c4 = *(const float4*)&sCt[i4];
        float4 v;
        v.x = fmaf(u1, q1.x, fmaf(u0, q0.x, h4.x));
        v.y = fmaf(u1, q1.y, fmaf(u0, q0.y, h4.y));
        v.z = fmaf(u1, q1.z, fmaf(u0, q0.z, h4.z));
        v.w = fmaf(u1, q1.w, fmaf(u0, q0.w, h4.w));
        *(float4*)&orow[i4] = v;
        ca = fmaf(c4.x, v.x, ca); ca = fmaf(c4.y, v.y, ca);
        ca = fmaf(c4.z, v.z, ca); ca = fmaf(c4.w, v.w, ca);
    }
    #pragma unroll
    for (int o = 8; o; o >>= 1) ca += __shfl_xor_sync(0xffffffffu, ca, o, 16);
    if (lane16 == 0) g_cab[mat][l * SS + s0 + row] = ca;
}

// ---------------------------------------------------------------------------
// gelu pair (tanh-only accumulator; the Sum(w) part is rank-1 -> Ca+Cb):
//   z = a+b;  arg = z*(C0 + C1*z^2);  acc += (ct*z)*tanh(arg)   [f32x2]
// ---------------------------------------------------------------------------
__device__ __forceinline__ void gelu2t(ull a2, ull b2, ull c2, ull C0, ull C1,
                                       ull& acc_t) {
    ull z2; ADD2(z2, a2, b2);
    ull q2; MUL2(q2, z2, z2);
    ull p2; FMA2(p2, C1, q2, C0);
    ull g2; MUL2(g2, z2, p2);
    float glo, ghi;
    asm("mov.b64 {%0,%1}, %2;" : "=f"(glo), "=f"(ghi) : "l"(g2));
    float tlo, thi;
    asm("tanh.approx.f32 %0, %1;" : "=f"(tlo) : "f"(glo));
    asm("tanh.approx.f32 %0, %1;" : "=f"(thi) : "f"(ghi));
    ull th2;
    asm("mov.b64 %0, {%1,%2};" : "=l"(th2) : "f"(tlo), "f"(thi));
    ull w2; MUL2(w2, c2, z2);
    FMA2(acc_t, w2, th2, acc_t);
}

// ---------------------------------------------------------------------------
// Main: out[l,s,t] = sum_i (ct*z)*tanh + Ca[l,s] + Cb[l,t]
// 64 threads, 16x16 tile, 2s x 2t per thread, grid 640.
// ---------------------------------------------------------------------------
#define STRD 68

__global__ void __launch_bounds__(64, 12) main_kernel(float* __restrict__ out) {
    const int l  = blockIdx.z;
    const int s0 = blockIdx.y * 16;
    const int t0 = blockIdx.x * 16;
    const int tid = threadIdx.x;
    const int txx = tid & 7;
    const int tyy = tid >> 3;

    __shared__ __align__(16) float sA[16][STRD];
    __shared__ __align__(16) float sB[16][STRD];
    __shared__ __align__(16) float sC[64];
    __shared__ float sCa[16], sCb[16];

    if (tid < 16)      sCa[tid]      = g_cab[0][l * SS + s0 + tid];
    else if (tid < 32) sCb[tid - 16] = g_cab[1][l * SS + t0 + tid - 16];

    const float* __restrict__ Abase = &g_ab[0][(l * SS + s0) * HH];
    const float* __restrict__ Bbase = &g_ab[1][(l * SS + t0) * HH];
    const float* __restrict__ Cbase = &g_ct[l * HH];

    ull C0_2, C1_2;
    asm("mov.b64 %0, {%1,%1};" : "=l"(C0_2) : "f"(0.7978845608028654f));
    asm("mov.b64 %0, {%1,%1};" : "=l"(C1_2) : "f"(0.035677408136300125f));

    ull t00 = 0, t01 = 0, t10 = 0, t11 = 0;

    for (int c0 = 0; c0 < HH; c0 += 64) {
        __syncthreads();
        #pragma unroll
        for (int e = tid; e < 256; e += 64) {
            int r = e >> 4, c4 = (e & 15) << 2;
            *(float4*)&sA[r][c4] = *(const float4*)(Abase + r * HH + c0 + c4);
            *(float4*)&sB[r][c4] = *(const float4*)(Bbase + r * HH + c0 + c4);
        }
        if (tid < 16) *(float4*)&sC[tid * 4] = *(const float4*)(Cbase + c0 + tid * 4);
        __syncthreads();

        #pragma unroll 4
        for (int ii = 0; ii < 64; ii += 2) {
            ull a0 = *(const ull*)&sA[tyy][ii];
            ull a1 = *(const ull*)&sA[tyy + 8][ii];
            ull b0 = *(const ull*)&sB[txx][ii];
            ull b1 = *(const ull*)&sB[txx + 8][ii];
            ull cc = *(const ull*)&sC[ii];
            gelu2t(a0, b0, cc, C0_2, C1_2, t00);
            gelu2t(a0, b1, cc, C0_2, C1_2, t01);
            gelu2t(a1, b0, cc, C0_2, C1_2, t10);
            gelu2t(a1, b1, cc, C0_2, C1_2, t11);
        }
    }

    float xlo, xhi;
    float caA = sCa[tyy], caB = sCa[tyy + 8];
    float cbA = sCb[txx], cbB = sCb[txx + 8];
    const int sa = s0 + tyy, sb = s0 + tyy + 8;
    const int ta = t0 + txx, tb = t0 + txx + 8;

    asm("mov.b64 {%0,%1}, %2;" : "=f"(xlo), "=f"(xhi) : "l"(t00));
    out[(l * SS + sa) * SS + ta] = (xlo + xhi) + caA + cbA;
    asm("mov.b64 {%0,%1}, %2;" : "=f"(xlo), "=f"(xhi) : "l"(t01));
    out[(l * SS + sa) * SS + tb] = (xlo + xhi) + caA + cbB;
    asm("mov.b64 {%0,%1}, %2;" : "=f"(xlo), "=f"(xhi) : "l"(t10));
    out[(l * SS + sb) * SS + ta] = (xlo + xhi) + caB + cbA;
    asm("mov.b64 {%0,%1}, %2;" : "=f"(xlo), "=f"(xhi) : "l"(t11));
    out[(l * SS + sb) * SS + tb] = (xlo + xhi) + caB + cbB;
}

// ---------------------------------------------------------------------------
extern "C" void kernel_launch(void* const* d_in, const int* in_sizes, int n_in,
                              void* d_out, int out_size) {
    const float* x    = (const float*)d_in[0];
    const float* Wsrc = (const float*)d_in[1];
    const float* bsrc = (const float*)d_in[2];
    const float* Wtgt = (const float*)d_in[3];
    const float* btgt = (const float*)d_in[4];
    const float* Asrc = (const float*)d_in[5];
    const float* Bsrc = (const float*)d_in[6];
    const float* Atgt = (const float*)d_in[7];
    const float* Btgt = (const float*)d_in[8];
    const float* cls  = (const float*)d_in[9];
    float* out = (float*)d_out;

    prep_kernel    <<<528, 256>>>(x, Wsrc, Wtgt, Asrc, Bsrc, Atgt, Btgt, cls);
    reduce_h_kernel<<<192, 256>>>(bsrc, btgt);
    expand_kernel  <<<dim3(8, LL, 2), 256>>>();
    main_kernel    <<<dim3(8, 8, LL), 64>>>(out);
}

// round 11
// speedup vs baseline: 1.1378x; 1.1378x over previous
#include <cuda_runtime.h>
#include <math.h>

#define HH 768
#define SS 128
#define LL 10

typedef unsigned long long ull;

// Scratch (no allocation allowed)
__device__ float g_hp[4][2][SS * HH];      // k-split partials of x@W
__device__ float g_h[2][SS * HH];          // x@W + bias (reduced)
__device__ float g_u[2][SS * 20];          // x@A   (rl = r*10+l)
__device__ float g_Bt[2 * LL * 2 * HH];    // Bt[mat][l][r][i] = B[mat][(r*H+i)*L + l]
__device__ float g_ct[LL * HH];            // ct[l][i] = 0.5 * classifier[i*L + l]
__device__ float g_ab[2][LL * SS * HH];    // a[l][s][i], b[l][t][i]
__device__ float g_cab[2][LL * SS];        // Ca[l][s] = sum_i ct*a ; Cb[l][t]
__device__ float g_po[2][LL * SS * SS];    // i-split partial outputs

// Packed f32x2 ops (sm_100+). ptxas will not auto-emit these.
#define ADD2(o,a,b)   asm("add.rn.f32x2 %0,%1,%2;"    : "=l"(o) : "l"(a), "l"(b))
#define MUL2(o,a,b)   asm("mul.rn.f32x2 %0,%1,%2;"    : "=l"(o) : "l"(a), "l"(b))
#define FMA2(o,a,b,c) asm("fma.rn.f32x2 %0,%1,%2,%3;" : "=l"(o) : "l"(a), "l"(b), "l"(c))

// ---------------------------------------------------------------------------
// Prep kernel, 528 blocks x 256 threads:
//   blocks 0..383   : gemm partials (2 mats x 12 i-tiles x 4 s-tiles x 4 ksplit)
//   blocks 384..511 : u[s][r][l]
//   blocks 512..527 : transposes (Bt, ct)
// ---------------------------------------------------------------------------
__global__ void __launch_bounds__(256) prep_kernel(
        const float* __restrict__ x,
        const float* __restrict__ Wsrc, const float* __restrict__ Wtgt,
        const float* __restrict__ Asrc, const float* __restrict__ Bsrc,
        const float* __restrict__ Atgt, const float* __restrict__ Btgt,
        const float* __restrict__ cls) {
    const int bid = blockIdx.x;
    const int tid = threadIdx.x;

    if (bid < 384) {
        // ---- gemm partial: 32s x 64i tile, k-range 192 (6 chunks of 32) ----
        const int p    = bid & 3;
        const int rest = bid >> 2;
        const int it   = rest % 12;
        const int st   = (rest / 12) % 4;
        const int mat  = rest / 48;
        const float* __restrict__ Wm = mat ? Wtgt : Wsrc;
        const int i0 = it * 64;
        const int s0 = st * 32;
        const int kb = p * 192;

        __shared__ float sX[32][34];                  // [k][s], pad 34: 8B-aligned
        __shared__ __align__(16) float sW[32][64];    // [k][i]

        const int tx  = tid & 15;       // i (4 each)
        const int ty  = tid >> 4;       // s (2 each)
        const int kx  = tid & 31;       // staging: k lane
        const int sw  = tid >> 5;       // staging: s base (rows sw+8j)
        const int kkw = tid >> 4;       // staging: W row
        const int iw  = (tid & 15) * 4; // staging: W col

        ull acc00 = 0, acc01 = 0, acc10 = 0, acc11 = 0;

        float px[4]; float4 pw0, pw1;
        #pragma unroll
        for (int j = 0; j < 4; j++)
            px[j] = x[(s0 + sw + 8 * j) * HH + kb + kx];
        pw0 = *(const float4*)&Wm[(kb + kkw) * HH + i0 + iw];
        pw1 = *(const float4*)&Wm[(kb + 16 + kkw) * HH + i0 + iw];

        for (int c = 0; c < 6; c++) {
            __syncthreads();
            #pragma unroll
            for (int j = 0; j < 4; j++) sX[kx][sw + 8 * j] = px[j];
            *(float4*)&sW[kkw][iw]      = pw0;
            *(float4*)&sW[kkw + 16][iw] = pw1;
            __syncthreads();
            if (c < 5) {
                const int k0 = kb + (c + 1) * 32;
                #pragma unroll
                for (int j = 0; j < 4; j++)
                    px[j] = x[(s0 + sw + 8 * j) * HH + k0 + kx];
                pw0 = *(const float4*)&Wm[(k0 + kkw) * HH + i0 + iw];
                pw1 = *(const float4*)&Wm[(k0 + 16 + kkw) * HH + i0 + iw];
            }
            #pragma unroll
            for (int kk = 0; kk < 32; kk++) {
                float2 a2 = *(const float2*)&sX[kk][ty * 2];
                ull b01 = *(const ull*)&sW[kk][tx * 4];
                ull b23 = *(const ull*)&sW[kk][tx * 4 + 2];
                ull a0d, a1d;
                asm("mov.b64 %0,{%1,%1};" : "=l"(a0d) : "f"(a2.x));
                asm("mov.b64 %0,{%1,%1};" : "=l"(a1d) : "f"(a2.y));
                FMA2(acc00, a0d, b01, acc00);
                FMA2(acc01, a0d, b23, acc01);
                FMA2(acc10, a1d, b01, acc10);
                FMA2(acc11, a1d, b23, acc11);
            }
        }
        float v[2][4];
        asm("mov.b64 {%0,%1}, %2;" : "=f"(v[0][0]), "=f"(v[0][1]) : "l"(acc00));
        asm("mov.b64 {%0,%1}, %2;" : "=f"(v[0][2]), "=f"(v[0][3]) : "l"(acc01));
        asm("mov.b64 {%0,%1}, %2;" : "=f"(v[1][0]), "=f"(v[1][1]) : "l"(acc10));
        asm("mov.b64 {%0,%1}, %2;" : "=f"(v[1][2]), "=f"(v[1][3]) : "l"(acc11));
        #pragma unroll
        for (int i = 0; i < 2; i++)
            #pragma unroll
            for (int j = 0; j < 4; j++) {
                int s  = s0 + ty * 2 + i;
                int ii = i0 + tx * 4 + j;
                g_hp[p][mat][s * HH + ii] = v[i][j];
            }
    } else if (bid < 512) {
        // ---- u[s][r][l] = sum_h x[s,h]*A[h,r,l], 4-way k-split ----
        __shared__ float sx[HH];
        __shared__ float spart[4][40];
        const int s = bid - 384;
        for (int e = tid; e < HH; e += 256) sx[e] = x[s * HH + e];
        __syncthreads();
        const int seg = tid >> 6;
        const int j   = tid & 63;
        if (j < 40) {
            const int mat = j / 20, rl = j % 20;
            const float* __restrict__ A = mat ? Atgt : Asrc;
            float acc = 0.f;
            const int h0 = seg * 192;
            #pragma unroll 8
            for (int h = h0; h < h0 + 192; h++)
                acc = fmaf(sx[h], A[h * 20 + rl], acc);
            spart[seg][j] = acc;
        }
        __syncthreads();
        if (tid < 40) {
            float vv = spart[0][tid] + spart[1][tid] + spart[2][tid] + spart[3][tid];
            g_u[tid / 20][s * 20 + tid % 20] = vv;
        }
    } else {
        // ---- transposes: Bt and ct ----
        const int idx0 = (bid - 512) * 256 + tid;
        for (int n = idx0; n < 2 * LL * 2 * HH; n += 16 * 256) {
            int i   = n % HH;
            int rem = n / HH;
            int r   = rem % 2;
            int l   = (rem / 2) % LL;
            int mat = rem / (2 * LL);
            const float* __restrict__ Bm = mat ? Btgt : Bsrc;
            g_Bt[((mat * LL + l) * 2 + r) * HH + i] = Bm[(r * HH + i) * LL + l];
        }
        for (int n = idx0; n < LL * HH; n += 16 * 256) {
            int i = n % HH, l = n / HH;
            g_ct[l * HH + i] = 0.5f * cls[i * LL + l];
        }
    }
}

// ---------------------------------------------------------------------------
// Reduce kernel: g_h = sum_p g_hp[p] + bias.  192 blocks x 256 thr, 1 float4 each.
// ---------------------------------------------------------------------------
__global__ void __launch_bounds__(256) reduce_h_kernel(
        const float* __restrict__ bsrc, const float* __restrict__ btgt) {
    const int n4  = blockIdx.x * 256 + threadIdx.x;    // float4 index
    const int mat = n4 / (SS * HH / 4);
    const int off = (n4 - mat * (SS * HH / 4)) * 4;
    const int i   = off % HH;
    const float* __restrict__ bm = mat ? btgt : bsrc;

    float4 h0 = *(const float4*)&g_hp[0][mat][off];
    float4 h1 = *(const float4*)&g_hp[1][mat][off];
    float4 h2 = *(const float4*)&g_hp[2][mat][off];
    float4 h3 = *(const float4*)&g_hp[3][mat][off];
    float4 bb = *(const float4*)&bm[i];
    float4 v;
    v.x = ((h0.x + h1.x) + (h2.x + h3.x)) + bb.x;
    v.y = ((h0.y + h1.y) + (h2.y + h3.y)) + bb.y;
    v.z = ((h0.z + h1.z) + (h2.z + h3.z)) + bb.z;
    v.w = ((h0.w + h1.w) + (h2.w + h3.w)) + bb.w;
    *(float4*)&g_h[mat][off] = v;
}

// ---------------------------------------------------------------------------
// Expand kernel: ab = h + u0*Bt0 + u1*Bt1 ; Ca/Cb = sum_i ct*ab  (rank-1 part)
// grid (8 s-chunks, LL, 2 mats) = 160 blocks, 256 threads.
// ---------------------------------------------------------------------------
__global__ void __launch_bounds__(256) expand_kernel() {
    const int mat = blockIdx.z;
    const int l   = blockIdx.y;
    const int s0  = blockIdx.x * 16;
    const int tid = threadIdx.x;

    __shared__ __align__(16) float sBt0[HH], sBt1[HH], sCt[HH];
    __shared__ float su[16][2];

    for (int e = tid; e < HH; e += 256) {
        sBt0[e] = g_Bt[((mat * LL + l) * 2 + 0) * HH + e];
        sBt1[e] = g_Bt[((mat * LL + l) * 2 + 1) * HH + e];
        sCt[e]  = g_ct[l * HH + e];
    }
    if (tid < 32) {
        int si = tid >> 1, r = tid & 1;
        su[si][r] = g_u[mat][(s0 + si) * 20 + r * 10 + l];
    }
    __syncthreads();

    const int row    = tid >> 4;
    const int lane16 = tid & 15;
    const float u0 = su[row][0], u1 = su[row][1];
    const float* __restrict__ hrow = &g_h[mat][(s0 + row) * HH];
    float* __restrict__ orow = &g_ab[mat][(l * SS + s0 + row) * HH];

    float ca = 0.f;
    #pragma unroll
    for (int j = 0; j < 12; j++) {
        int i4 = lane16 * 4 + j * 64;
        float4 h4 = *(const float4*)&hrow[i4];
        float4 q0 = *(const float4*)&sBt0[i4];
        float4 q1 = *(const float4*)&sBt1[i4];
        float4 c4 = *(const float4*)&sCt[i4];
        float4 v;
        v.x = fmaf(u1, q1.x, fmaf(u0, q0.x, h4.x));
        v.y = fmaf(u1, q1.y, fmaf(u0, q0.y, h4.y));
        v.z = fmaf(u1, q1.z, fmaf(u0, q0.z, h4.z));
        v.w = fmaf(u1, q1.w, fmaf(u0, q0.w, h4.w));
        *(float4*)&orow[i4] = v;
        ca = fmaf(c4.x, v.x, ca); ca = fmaf(c4.y, v.y, ca);
        ca = fmaf(c4.z, v.z, ca); ca = fmaf(c4.w, v.w, ca);
    }
    #pragma unroll
    for (int o = 8; o; o >>= 1) ca += __shfl_xor_sync(0xffffffffu, ca, o, 16);
    if (lane16 == 0) g_cab[mat][l * SS + s0 + row] = ca;
}

// ---------------------------------------------------------------------------
// gelu pair (tanh-only accumulator; the Sum(w) part is rank-1 -> Ca+Cb):
//   z = a+b;  arg = z*(C0 + C1*z^2);  acc += (ct*z)*tanh(arg)   [f32x2]
// ---------------------------------------------------------------------------
__device__ __forceinline__ void gelu2t(ull a2, ull b2, ull c2, ull C0, ull C1,
                                       ull& acc_t) {
    ull z2; ADD2(z2, a2, b2);
    ull q2; MUL2(q2, z2, z2);
    ull p2; FMA2(p2, C1, q2, C0);
    ull g2; MUL2(g2, z2, p2);
    float glo, ghi;
    asm("mov.b64 {%0,%1}, %2;" : "=f"(glo), "=f"(ghi) : "l"(g2));
    float tlo, thi;
    asm("tanh.approx.f32 %0, %1;" : "=f"(tlo) : "f"(glo));
    asm("tanh.approx.f32 %0, %1;" : "=f"(thi) : "f"(ghi));
    ull th2;
    asm("mov.b64 %0, {%1,%2};" : "=l"(th2) : "f"(tlo), "f"(thi));
    ull w2; MUL2(w2, c2, z2);
    FMA2(acc_t, w2, th2, acc_t);
}

// ---------------------------------------------------------------------------
// Main: partial[ks][l,s,t] = sum_{i in half ks} (ct*z)*tanh
// grid (8 t-tiles x 2 ksplit, 8 s-tiles, 10 l) = 1280 blocks, 64 threads,
// 16x16 tile, 2s x 2t per thread. i-split doubles resident warps (occ fix).
// ---------------------------------------------------------------------------
#define STRD 68

__global__ void __launch_bounds__(64, 12) main_kernel() {
    const int l  = blockIdx.z;
    const int s0 = blockIdx.y * 16;
    const int tt = blockIdx.x & 7;
    const int ks = blockIdx.x >> 3;
    const int t0 = tt * 16;
    const int cb = ks * 384;            // i-range [cb, cb+384)
    const int tid = threadIdx.x;
    const int txx = tid & 7;
    const int tyy = tid >> 3;

    __shared__ __align__(16) float sA[16][STRD];
    __shared__ __align__(16) float sB[16][STRD];
    __shared__ __align__(16) float sC[64];

    const float* __restrict__ Abase = &g_ab[0][(l * SS + s0) * HH];
    const float* __restrict__ Bbase = &g_ab[1][(l * SS + t0) * HH];
    const float* __restrict__ Cbase = &g_ct[l * HH];

    ull C0_2, C1_2;
    asm("mov.b64 %0, {%1,%1};" : "=l"(C0_2) : "f"(0.7978845608028654f));
    asm("mov.b64 %0, {%1,%1};" : "=l"(C1_2) : "f"(0.035677408136300125f));

    ull t00 = 0, t01 = 0, t10 = 0, t11 = 0;

    for (int c0 = cb; c0 < cb + 384; c0 += 64) {
        __syncthreads();
        #pragma unroll
        for (int e = tid; e < 256; e += 64) {
            int r = e >> 4, c4 = (e & 15) << 2;
            *(float4*)&sA[r][c4] = *(const float4*)(Abase + r * HH + c0 + c4);
            *(float4*)&sB[r][c4] = *(const float4*)(Bbase + r * HH + c0 + c4);
        }
        if (tid < 16) *(float4*)&sC[tid * 4] = *(const float4*)(Cbase + c0 + tid * 4);
        __syncthreads();

        #pragma unroll 4
        for (int ii = 0; ii < 64; ii += 2) {
            ull a0 = *(const ull*)&sA[tyy][ii];
            ull a1 = *(const ull*)&sA[tyy + 8][ii];
            ull b0 = *(const ull*)&sB[txx][ii];
            ull b1 = *(const ull*)&sB[txx + 8][ii];
            ull cc = *(const ull*)&sC[ii];
            gelu2t(a0, b0, cc, C0_2, C1_2, t00);
            gelu2t(a0, b1, cc, C0_2, C1_2, t01);
            gelu2t(a1, b0, cc, C0_2, C1_2, t10);
            gelu2t(a1, b1, cc, C0_2, C1_2, t11);
        }
    }

    float xlo, xhi;
    const int sa = s0 + tyy, sb = s0 + tyy + 8;
    const int ta = t0 + txx, tb = t0 + txx + 8;
    float* __restrict__ po = g_po[ks];

    asm("mov.b64 {%0,%1}, %2;" : "=f"(xlo), "=f"(xhi) : "l"(t00));
    po[(l * SS + sa) * SS + ta] = xlo + xhi;
    asm("mov.b64 {%0,%1}, %2;" : "=f"(xlo), "=f"(xhi) : "l"(t01));
    po[(l * SS + sa) * SS + tb] = xlo + xhi;
    asm("mov.b64 {%0,%1}, %2;" : "=f"(xlo), "=f"(xhi) : "l"(t10));
    po[(l * SS + sb) * SS + ta] = xlo + xhi;
    asm("mov.b64 {%0,%1}, %2;" : "=f"(xlo), "=f"(xhi) : "l"(t11));
    po[(l * SS + sb) * SS + tb] = xlo + xhi;
}

// ---------------------------------------------------------------------------
// Combine: out = po[0] + po[1] + Ca[l,s] + Cb[l,t].  640 x 256, coalesced.
// ---------------------------------------------------------------------------
__global__ void __launch_bounds__(256) combine_kernel(float* __restrict__ out) {
    const int idx = blockIdx.x * 256 + threadIdx.x;   // over 163840
    const int l   = idx >> 14;
    const int rem = idx & 16383;
    const int s   = rem >> 7;
    const int t   = rem & 127;
    out[idx] = (g_po[0][idx] + g_po[1][idx])
             + g_cab[0][l * SS + s] + g_cab[1][l * SS + t];
}

// ---------------------------------------------------------------------------
extern "C" void kernel_launch(void* const* d_in, const int* in_sizes, int n_in,
                              void* d_out, int out_size) {
    const float* x    = (const float*)d_in[0];
    const float* Wsrc = (const float*)d_in[1];
    const float* bsrc = (const float*)d_in[2];
    const float* Wtgt = (const float*)d_in[3];
    const float* btgt = (const float*)d_in[4];
    const float* Asrc = (const float*)d_in[5];
    const float* Bsrc = (const float*)d_in[6];
    const float* Atgt = (const float*)d_in[7];
    const float* Btgt = (const float*)d_in[8];
    const float* cls  = (const float*)d_in[9];
    float* out = (float*)d_out;

    prep_kernel    <<<528, 256>>>(x, Wsrc, Wtgt, Asrc, Bsrc, Atgt, Btgt, cls);
    reduce_h_kernel<<<192, 256>>>(bsrc, btgt);
    expand_kernel  <<<dim3(8, LL, 2), 256>>>();
    main_kernel    <<<dim3(16, 8, LL), 64>>>();
    combine_kernel <<<640, 256>>>(out);
}

// round 12
// speedup vs baseline: 1.2063x; 1.0602x over previous
#include <cuda_runtime.h>
#include <math.h>

#define HH 768
#define SS 128
#define LL 10

typedef unsigned long long ull;

// Scratch (no allocation allowed)
__device__ float g_hp[4][2][SS * HH];      // k-split partials of x@W
__device__ float g_h[2][SS * HH];          // x@W + bias (reduced)
__device__ float g_u[2][SS * 20];          // x@A   (rl = r*10+l)
__device__ float g_Bt[2 * LL * 2 * HH];    // Bt[mat][l][r][i] = B[mat][(r*H+i)*L + l]
__device__ float g_ct[LL * HH];            // ct[l][i] = 0.5 * classifier[i*L + l]
__device__ float g_ab[2][LL * SS * HH];    // a[l][s][i], b[l][t][i]
__device__ float g_cab[2][LL * SS];        // Ca[l][s] = sum_i ct*a ; Cb[l][t]
__device__ float g_po[4][LL * SS * SS];    // i-split partial outputs

// Packed f32x2 ops (sm_100+). ptxas will not auto-emit these.
#define ADD2(o,a,b)   asm("add.rn.f32x2 %0,%1,%2;"    : "=l"(o) : "l"(a), "l"(b))
#define MUL2(o,a,b)   asm("mul.rn.f32x2 %0,%1,%2;"    : "=l"(o) : "l"(a), "l"(b))
#define FMA2(o,a,b,c) asm("fma.rn.f32x2 %0,%1,%2,%3;" : "=l"(o) : "l"(a), "l"(b), "l"(c))

// ---------------------------------------------------------------------------
// Prep kernel, 528 blocks x 256 threads:
//   blocks 0..383   : gemm partials (2 mats x 12 i-tiles x 4 s-tiles x 4 ksplit)
//   blocks 384..511 : u[s][r][l]
//   blocks 512..527 : transposes (Bt, ct)
// ---------------------------------------------------------------------------
__global__ void __launch_bounds__(256) prep_kernel(
        const float* __restrict__ x,
        const float* __restrict__ Wsrc, const float* __restrict__ Wtgt,
        const float* __restrict__ Asrc, const float* __restrict__ Bsrc,
        const float* __restrict__ Atgt, const float* __restrict__ Btgt,
        const float* __restrict__ cls) {
    const int bid = blockIdx.x;
    const int tid = threadIdx.x;

    if (bid < 384) {
        // ---- gemm partial: 32s x 64i tile, k-range 192 (6 chunks of 32) ----
        const int p    = bid & 3;
        const int rest = bid >> 2;
        const int it   = rest % 12;
        const int st   = (rest / 12) % 4;
        const int mat  = rest / 48;
        const float* __restrict__ Wm = mat ? Wtgt : Wsrc;
        const int i0 = it * 64;
        const int s0 = st * 32;
        const int kb = p * 192;

        __shared__ float sX[32][34];                  // [k][s], pad 34: 8B-aligned
        __shared__ __align__(16) float sW[32][64];    // [k][i]

        const int tx  = tid & 15;       // i (4 each)
        const int ty  = tid >> 4;       // s (2 each)
        const int kx  = tid & 31;       // staging: k lane
        const int sw  = tid >> 5;       // staging: s base (rows sw+8j)
        const int kkw = tid >> 4;       // staging: W row
        const int iw  = (tid & 15) * 4; // staging: W col

        ull acc00 = 0, acc01 = 0, acc10 = 0, acc11 = 0;

        float px[4]; float4 pw0, pw1;
        #pragma unroll
        for (int j = 0; j < 4; j++)
            px[j] = x[(s0 + sw + 8 * j) * HH + kb + kx];
        pw0 = *(const float4*)&Wm[(kb + kkw) * HH + i0 + iw];
        pw1 = *(const float4*)&Wm[(kb + 16 + kkw) * HH + i0 + iw];

        for (int c = 0; c < 6; c++) {
            __syncthreads();
            #pragma unroll
            for (int j = 0; j < 4; j++) sX[kx][sw + 8 * j] = px[j];
            *(float4*)&sW[kkw][iw]      = pw0;
            *(float4*)&sW[kkw + 16][iw] = pw1;
            __syncthreads();
            if (c < 5) {
                const int k0 = kb + (c + 1) * 32;
                #pragma unroll
                for (int j = 0; j < 4; j++)
                    px[j] = x[(s0 + sw + 8 * j) * HH + k0 + kx];
                pw0 = *(const float4*)&Wm[(k0 + kkw) * HH + i0 + iw];
                pw1 = *(const float4*)&Wm[(k0 + 16 + kkw) * HH + i0 + iw];
            }
            #pragma unroll
            for (int kk = 0; kk < 32; kk++) {
                float2 a2 = *(const float2*)&sX[kk][ty * 2];
                ull b01 = *(const ull*)&sW[kk][tx * 4];
                ull b23 = *(const ull*)&sW[kk][tx * 4 + 2];
                ull a0d, a1d;
                asm("mov.b64 %0,{%1,%1};" : "=l"(a0d) : "f"(a2.x));
                asm("mov.b64 %0,{%1,%1};" : "=l"(a1d) : "f"(a2.y));
                FMA2(acc00, a0d, b01, acc00);
                FMA2(acc01, a0d, b23, acc01);
                FMA2(acc10, a1d, b01, acc10);
                FMA2(acc11, a1d, b23, acc11);
            }
        }
        float v[2][4];
        asm("mov.b64 {%0,%1}, %2;" : "=f"(v[0][0]), "=f"(v[0][1]) : "l"(acc00));
        asm("mov.b64 {%0,%1}, %2;" : "=f"(v[0][2]), "=f"(v[0][3]) : "l"(acc01));
        asm("mov.b64 {%0,%1}, %2;" : "=f"(v[1][0]), "=f"(v[1][1]) : "l"(acc10));
        asm("mov.b64 {%0,%1}, %2;" : "=f"(v[1][2]), "=f"(v[1][3]) : "l"(acc11));
        #pragma unroll
        for (int i = 0; i < 2; i++)
            #pragma unroll
            for (int j = 0; j < 4; j++) {
                int s  = s0 + ty * 2 + i;
                int ii = i0 + tx * 4 + j;
                g_hp[p][mat][s * HH + ii] = v[i][j];
            }
    } else if (bid < 512) {
        // ---- u[s][r][l] = sum_h x[s,h]*A[h,r,l], 4-way k-split ----
        __shared__ float sx[HH];
        __shared__ float spart[4][40];
        const int s = bid - 384;
        for (int e = tid; e < HH; e += 256) sx[e] = x[s * HH + e];
        __syncthreads();
        const int seg = tid >> 6;
        const int j   = tid & 63;
        if (j < 40) {
            const int mat = j / 20, rl = j % 20;
            const float* __restrict__ A = mat ? Atgt : Asrc;
            float acc = 0.f;
            const int h0 = seg * 192;
            #pragma unroll 8
            for (int h = h0; h < h0 + 192; h++)
                acc = fmaf(sx[h], A[h * 20 + rl], acc);
            spart[seg][j] = acc;
        }
        __syncthreads();
        if (tid < 40) {
            float vv = spart[0][tid] + spart[1][tid] + spart[2][tid] + spart[3][tid];
            g_u[tid / 20][s * 20 + tid % 20] = vv;
        }
    } else {
        // ---- transposes: Bt and ct ----
        const int idx0 = (bid - 512) * 256 + tid;
        for (int n = idx0; n < 2 * LL * 2 * HH; n += 16 * 256) {
            int i   = n % HH;
            int rem = n / HH;
            int r   = rem % 2;
            int l   = (rem / 2) % LL;
            int mat = rem / (2 * LL);
            const float* __restrict__ Bm = mat ? Btgt : Bsrc;
            g_Bt[((mat * LL + l) * 2 + r) * HH + i] = Bm[(r * HH + i) * LL + l];
        }
        for (int n = idx0; n < LL * HH; n += 16 * 256) {
            int i = n % HH, l = n / HH;
            g_ct[l * HH + i] = 0.5f * cls[i * LL + l];
        }
    }
}

// ---------------------------------------------------------------------------
// Reduce kernel: g_h = sum_p g_hp[p] + bias.  192 blocks x 256 thr, 1 float4 each.
// ---------------------------------------------------------------------------
__global__ void __launch_bounds__(256) reduce_h_kernel(
        const float* __restrict__ bsrc, const float* __restrict__ btgt) {
    const int n4  = blockIdx.x * 256 + threadIdx.x;    // float4 index
    const int mat = n4 / (SS * HH / 4);
    const int off = (n4 - mat * (SS * HH / 4)) * 4;
    const int i   = off % HH;
    const float* __restrict__ bm = mat ? btgt : bsrc;

    float4 h0 = *(const float4*)&g_hp[0][mat][off];
    float4 h1 = *(const float4*)&g_hp[1][mat][off];
    float4 h2 = *(const float4*)&g_hp[2][mat][off];
    float4 h3 = *(const float4*)&g_hp[3][mat][off];
    float4 bb = *(const float4*)&bm[i];
    float4 v;
    v.x = ((h0.x + h1.x) + (h2.x + h3.x)) + bb.x;
    v.y = ((h0.y + h1.y) + (h2.y + h3.y)) + bb.y;
    v.z = ((h0.z + h1.z) + (h2.z + h3.z)) + bb.z;
    v.w = ((h0.w + h1.w) + (h2.w + h3.w)) + bb.w;
    *(float4*)&g_h[mat][off] = v;
}

// ---------------------------------------------------------------------------
// Expand kernel: ab = h + u0*Bt0 + u1*Bt1 ; Ca/Cb = sum_i ct*ab  (rank-1 part)
// grid (8 s-chunks, LL, 2 mats) = 160 blocks, 256 threads.
// ---------------------------------------------------------------------------
__global__ void __launch_bounds__(256) expand_kernel() {
    const int mat = blockIdx.z;
    const int l   = blockIdx.y;
    const int s0  = blockIdx.x * 16;
    const int tid = threadIdx.x;

    __shared__ __align__(16) float sBt0[HH], sBt1[HH], sCt[HH];
    __shared__ float su[16][2];

    for (int e = tid; e < HH; e += 256) {
        sBt0[e] = g_Bt[((mat * LL + l) * 2 + 0) * HH + e];
        sBt1[e] = g_Bt[((mat * LL + l) * 2 + 1) * HH + e];
        sCt[e]  = g_ct[l * HH + e];
    }
    if (tid < 32) {
        int si = tid >> 1, r = tid & 1;
        su[si][r] = g_u[mat][(s0 + si) * 20 + r * 10 + l];
    }
    __syncthreads();

    const int row    = tid >> 4;
    const int lane16 = tid & 15;
    const float u0 = su[row][0], u1 = su[row][1];
    const float* __restrict__ hrow = &g_h[mat][(s0 + row) * HH];
    float* __restrict__ orow = &g_ab[mat][(l * SS + s0 + row) * HH];

    float ca = 0.f;
    #pragma unroll
    for (int j = 0; j < 12; j++) {
        int i4 = lane16 * 4 + j * 64;
        float4 h4 = *(const float4*)&hrow[i4];
        float4 q0 = *(const float4*)&sBt0[i4];
        float4 q1 = *(const float4*)&sBt1[i4];
        float4 c4 = *(const float4*)&sCt[i4];
        float4 v;
        v.x = fmaf(u1, q1.x, fmaf(u0, q0.x, h4.x));
        v.y = fmaf(u1, q1.y, fmaf(u0, q0.y, h4.y));
        v.z = fmaf(u1, q1.z, fmaf(u0, q0.z, h4.z));
        v.w = fmaf(u1, q1.w, fmaf(u0, q0.w, h4.w));
        *(float4*)&orow[i4] = v;
        ca = fmaf(c4.x, v.x, ca); ca = fmaf(c4.y, v.y, ca);
        ca = fmaf(c4.z, v.z, ca); ca = fmaf(c4.w, v.w, ca);
    }
    #pragma unroll
    for (int o = 8; o; o >>= 1) ca += __shfl_xor_sync(0xffffffffu, ca, o, 16);
    if (lane16 == 0) g_cab[mat][l * SS + s0 + row] = ca;
}

// ---------------------------------------------------------------------------
// gelu pair (tanh-only accumulator; the Sum(w) part is rank-1 -> Ca+Cb):
//   z = a+b;  arg = z*(C0 + C1*z^2);  acc += (ct*z)*tanh(arg)   [f32x2]
// ---------------------------------------------------------------------------
__device__ __forceinline__ void gelu2t(ull a2, ull b2, ull c2, ull C0, ull C1,
                                       ull& acc_t) {
    ull z2; ADD2(z2, a2, b2);
    ull q2; MUL2(q2, z2, z2);
    ull p2; FMA2(p2, C1, q2, C0);
    ull g2; MUL2(g2, z2, p2);
    float glo, ghi;
    asm("mov.b64 {%0,%1}, %2;" : "=f"(glo), "=f"(ghi) : "l"(g2));
    float tlo, thi;
    asm("tanh.approx.f32 %0, %1;" : "=f"(tlo) : "f"(glo));
    asm("tanh.approx.f32 %0, %1;" : "=f"(thi) : "f"(ghi));
    ull th2;
    asm("mov.b64 %0, {%1,%2};" : "=l"(th2) : "f"(tlo), "f"(thi));
    ull w2; MUL2(w2, c2, z2);
    FMA2(acc_t, w2, th2, acc_t);
}

// ---------------------------------------------------------------------------
// Main: partial[ks][l,s,t] = sum_{i in quarter ks} (ct*z)*tanh
// grid (8 t-tiles x 4 ksplit, 8 s-tiles, 10 l) = 2560 blocks, 64 threads,
// 16x16 tile, 2s x 2t per thread. 4-way i-split -> ~34 warps/SM.
// ---------------------------------------------------------------------------
#define STRD 68

__global__ void __launch_bounds__(64, 12) main_kernel() {
    const int l  = blockIdx.z;
    const int s0 = blockIdx.y * 16;
    const int tt = blockIdx.x & 7;
    const int ks = blockIdx.x >> 3;     // 0..3
    const int t0 = tt * 16;
    const int cb = ks * 192;            // i-range [cb, cb+192)
    const int tid = threadIdx.x;
    const int txx = tid & 7;
    const int tyy = tid >> 3;

    __shared__ __align__(16) float sA[16][STRD];
    __shared__ __align__(16) float sB[16][STRD];
    __shared__ __align__(16) float sC[64];

    const float* __restrict__ Abase = &g_ab[0][(l * SS + s0) * HH];
    const float* __restrict__ Bbase = &g_ab[1][(l * SS + t0) * HH];
    const float* __restrict__ Cbase = &g_ct[l * HH];

    ull C0_2, C1_2;
    asm("mov.b64 %0, {%1,%1};" : "=l"(C0_2) : "f"(0.7978845608028654f));
    asm("mov.b64 %0, {%1,%1};" : "=l"(C1_2) : "f"(0.035677408136300125f));

    ull t00 = 0, t01 = 0, t10 = 0, t11 = 0;

    for (int c0 = cb; c0 < cb + 192; c0 += 64) {
        __syncthreads();
        #pragma unroll
        for (int e = tid; e < 256; e += 64) {
            int r = e >> 4, c4 = (e & 15) << 2;
            *(float4*)&sA[r][c4] = *(const float4*)(Abase + r * HH + c0 + c4);
            *(float4*)&sB[r][c4] = *(const float4*)(Bbase + r * HH + c0 + c4);
        }
        if (tid < 16) *(float4*)&sC[tid * 4] = *(const float4*)(Cbase + c0 + tid * 4);
        __syncthreads();

        #pragma unroll 4
        for (int ii = 0; ii < 64; ii += 2) {
            ull a0 = *(const ull*)&sA[tyy][ii];
            ull a1 = *(const ull*)&sA[tyy + 8][ii];
            ull b0 = *(const ull*)&sB[txx][ii];
            ull b1 = *(const ull*)&sB[txx + 8][ii];
            ull cc = *(const ull*)&sC[ii];
            gelu2t(a0, b0, cc, C0_2, C1_2, t00);
            gelu2t(a0, b1, cc, C0_2, C1_2, t01);
            gelu2t(a1, b0, cc, C0_2, C1_2, t10);
            gelu2t(a1, b1, cc, C0_2, C1_2, t11);
        }
    }

    float xlo, xhi;
    const int sa = s0 + tyy, sb = s0 + tyy + 8;
    const int ta = t0 + txx, tb = t0 + txx + 8;
    float* __restrict__ po = g_po[ks];

    asm("mov.b64 {%0,%1}, %2;" : "=f"(xlo), "=f"(xhi) : "l"(t00));
    po[(l * SS + sa) * SS + ta] = xlo + xhi;
    asm("mov.b64 {%0,%1}, %2;" : "=f"(xlo), "=f"(xhi) : "l"(t01));
    po[(l * SS + sa) * SS + tb] = xlo + xhi;
    asm("mov.b64 {%0,%1}, %2;" : "=f"(xlo), "=f"(xhi) : "l"(t10));
    po[(l * SS + sb) * SS + ta] = xlo + xhi;
    asm("mov.b64 {%0,%1}, %2;" : "=f"(xlo), "=f"(xhi) : "l"(t11));
    po[(l * SS + sb) * SS + tb] = xlo + xhi;
}

// ---------------------------------------------------------------------------
// Combine: out = sum_ks po[ks] + Ca[l,s] + Cb[l,t].  640 x 256, coalesced.
// ---------------------------------------------------------------------------
__global__ void __launch_bounds__(256) combine_kernel(float* __restrict__ out) {
    const int idx = blockIdx.x * 256 + threadIdx.x;   // over 163840
    const int l   = idx >> 14;
    const int rem = idx & 16383;
    const int s   = rem >> 7;
    const int t   = rem & 127;
    out[idx] = ((g_po[0][idx] + g_po[1][idx]) + (g_po[2][idx] + g_po[3][idx]))
             + g_cab[0][l * SS + s] + g_cab[1][l * SS + t];
}

// ---------------------------------------------------------------------------
extern "C" void kernel_launch(void* const* d_in, const int* in_sizes, int n_in,
                              void* d_out, int out_size) {
    const float* x    = (const float*)d_in[0];
    const float* Wsrc = (const float*)d_in[1];
    const float* bsrc = (const float*)d_in[2];
    const float* Wtgt = (const float*)d_in[3];
    const float* btgt = (const float*)d_in[4];
    const float* Asrc = (const float*)d_in[5];
    const float* Bsrc = (const float*)d_in[6];
    const float* Atgt = (const float*)d_in[7];
    const float* Btgt = (const float*)d_in[8];
    const float* cls  = (const float*)d_in[9];
    float* out = (float*)d_out;

    prep_kernel    <<<528, 256>>>(x, Wsrc, Wtgt, Asrc, Bsrc, Atgt, Btgt, cls);
    reduce_h_kernel<<<192, 256>>>(bsrc, btgt);
    expand_kernel  <<<dim3(8, LL, 2), 256>>>();
    main_kernel    <<<dim3(32, 8, LL), 64>>>();
    combine_kernel <<<640, 256>>>(out);
}